// round 11
// baseline (speedup 1.0000x reference)
#include <cuda_runtime.h>
#include <math.h>
#include <stdint.h>

// ---------------------------------------------------------------------------
// GAT_linear_negbin: 3x GATConv (single head) + linear head.
// Round 11: shuffle-broadcast per-edge p/col for deg<=32 nodes (no g_p/g_pp
// round-trip; arithmetic identical). Fallback to scratch path for deg>32.
// ---------------------------------------------------------------------------

#define NMAX 50000
#define EMAX 800000

__device__ float  g_h1p[NMAX * 64];
__device__ float  g_h1 [NMAX * 64];
__device__ float  g_h23[NMAX * 64];   // cols 0-31: h1@W2, cols 32-63: h1@W3
__device__ float  g_es1[NMAX], g_ed1[NMAX];
__device__ float2 g_es23[NMAX];       // (es2, es3)
__device__ float2 g_ed23[NMAX];       // (ed2, ed3)
__device__ float2 g_dai[NMAX];        // (ed2, inv2) for edge-parallel alpha
__device__ float  g_p  [EMAX];        // fallback scratch (deg>32 only)
__device__ float2 g_pp [EMAX];        // fallback scratch (deg>32 only)
__device__ int    g_cnt[NMAX];        // zero at load; self-zeroed by scan1
__device__ int    g_rowptr[NMAX + 1];
__device__ int    g_fill[NMAX];
__device__ int    g_col[EMAX];
__device__ int    g_bsum[64];

// ---------------------------------------------------------------------------
__device__ __forceinline__ unsigned f2tf(float f) {
    unsigned r;
    asm("cvt.rna.tf32.f32 %0, %1;" : "=r"(r) : "f"(f));
    return r;
}

#define MMA(c0,c1,c2,c3,a0,a1,a2,a3,b0,b1)                                     \
    asm volatile(                                                              \
        "mma.sync.aligned.m16n8k8.row.col.f32.tf32.tf32.f32 "                  \
        "{%0,%1,%2,%3}, {%4,%5,%6,%7}, {%8,%9}, {%0,%1,%2,%3};"                \
        : "+f"(c0), "+f"(c1), "+f"(c2), "+f"(c3)                               \
        : "r"(a0), "r"(a1), "r"(a2), "r"(a3), "r"(b0), "r"(b1))

#define SPLIT_STORE(val, HI, LO)                                               \
    do { unsigned _hb = f2tf(val); float _hf = __uint_as_float(_hb);           \
         (HI) = _hf; (LO) = __uint_as_float(f2tf((val) - _hf)); } while (0)

#define LOAD_AFRAG(h0,h1,h2,h3,l0,l1,l2,l3,r0,kk)                              \
    do { h0 = __float_as_uint(Ah[(r0)][(kk) + tg]);                            \
         h1 = __float_as_uint(Ah[(r0) + 8][(kk) + tg]);                        \
         h2 = __float_as_uint(Ah[(r0)][(kk) + tg + 4]);                        \
         h3 = __float_as_uint(Ah[(r0) + 8][(kk) + tg + 4]);                    \
         l0 = __float_as_uint(Al[(r0)][(kk) + tg]);                            \
         l1 = __float_as_uint(Al[(r0) + 8][(kk) + tg]);                        \
         l2 = __float_as_uint(Al[(r0)][(kk) + tg + 4]);                        \
         l3 = __float_as_uint(Al[(r0) + 8][(kk) + tg + 4]); } while (0)

#define LOAD_BFRAG(h0,h1,l0,l1,c0,kk)                                          \
    do { h0 = __float_as_uint(Bh[(kk) + tg][(c0)]);                            \
         h1 = __float_as_uint(Bh[(kk) + tg + 4][(c0)]);                        \
         l0 = __float_as_uint(Bl[(kk) + tg][(c0)]);                            \
         l1 = __float_as_uint(Bl[(kk) + tg + 4][(c0)]); } while (0)

#define MMA3(c0,c1,c2,c3,ah0,ah1,ah2,ah3,al0,al1,al2,al3,bh0,bh1,bl0,bl1)      \
    do { MMA(c0,c1,c2,c3, ah0,ah1,ah2,ah3, bh0,bh1);                           \
         MMA(c0,c1,c2,c3, ah0,ah1,ah2,ah3, bl0,bl1);                           \
         MMA(c0,c1,c2,c3, al0,al1,al2,al3, bh0,bh1); } while (0)

// 3xTF32 TC GEMM + fused attention-coefficient epilogue.
template <int MODE>
__global__ __launch_bounds__(256) void k_gemm_tc(const float* __restrict__ Aarg,
                                                 const float* __restrict__ B1,
                                                 const float* __restrict__ B2,
                                                 const float* __restrict__ asA,
                                                 const float* __restrict__ adA,
                                                 const float* __restrict__ asB,
                                                 const float* __restrict__ adB,
                                                 int n) {
    constexpr int K = (MODE == 0) ? 256 : 64;
    constexpr int KC = 16;
    const float* A = (MODE == 0) ? Aarg : g_h1;
    float* C = (MODE == 0) ? g_h1p : g_h23;

    __shared__ float Ah[128][KC + 2];
    __shared__ float Al[128][KC + 2];
    __shared__ float Bh[KC][68];
    __shared__ float Bl[KC][68];
    __shared__ float sred[128][4];
    const int t = threadIdx.x;
    const int lane = t & 31, warp = t >> 5;
    const int wr = (warp & 3) * 32, wc = (warp >> 2) * 32;
    const int row0 = blockIdx.x * 128;
    const int g = lane >> 2, tg = lane & 3;

    {
        float* f = &sred[0][0];
        for (int i = t; i < 512; i += 256) f[i] = 0.f;
    }

    float c000 = 0.f, c001 = 0.f, c002 = 0.f, c003 = 0.f;
    float c010 = 0.f, c011 = 0.f, c012 = 0.f, c013 = 0.f;
    float c020 = 0.f, c021 = 0.f, c022 = 0.f, c023 = 0.f;
    float c030 = 0.f, c031 = 0.f, c032 = 0.f, c033 = 0.f;
    float c100 = 0.f, c101 = 0.f, c102 = 0.f, c103 = 0.f;
    float c110 = 0.f, c111 = 0.f, c112 = 0.f, c113 = 0.f;
    float c120 = 0.f, c121 = 0.f, c122 = 0.f, c123 = 0.f;
    float c130 = 0.f, c131 = 0.f, c132 = 0.f, c133 = 0.f;

    for (int kc = 0; kc < K; kc += KC) {
        {
            int ar = t >> 1, ak = (t & 1) * 8;
            float4 v0 = make_float4(0.f, 0.f, 0.f, 0.f), v1 = v0;
            if (row0 + ar < n) {
                const float* ap = A + (size_t)(row0 + ar) * K + kc + ak;
                v0 = *(const float4*)ap;
                v1 = *(const float4*)(ap + 4);
            }
            SPLIT_STORE(v0.x, Ah[ar][ak + 0], Al[ar][ak + 0]);
            SPLIT_STORE(v0.y, Ah[ar][ak + 1], Al[ar][ak + 1]);
            SPLIT_STORE(v0.z, Ah[ar][ak + 2], Al[ar][ak + 2]);
            SPLIT_STORE(v0.w, Ah[ar][ak + 3], Al[ar][ak + 3]);
            SPLIT_STORE(v1.x, Ah[ar][ak + 4], Al[ar][ak + 4]);
            SPLIT_STORE(v1.y, Ah[ar][ak + 5], Al[ar][ak + 5]);
            SPLIT_STORE(v1.z, Ah[ar][ak + 6], Al[ar][ak + 6]);
            SPLIT_STORE(v1.w, Ah[ar][ak + 7], Al[ar][ak + 7]);
        }
        {
            int bk = t >> 4, bn = (t & 15) * 4;
            const float* bp;
            if (MODE == 0) bp = B1 + (size_t)(kc + bk) * 64 + bn;
            else bp = (bn < 32) ? B1 + (size_t)(kc + bk) * 32 + bn
                                : B2 + (size_t)(kc + bk) * 32 + (bn - 32);
            float4 v = *(const float4*)bp;
            SPLIT_STORE(v.x, Bh[bk][bn + 0], Bl[bk][bn + 0]);
            SPLIT_STORE(v.y, Bh[bk][bn + 1], Bl[bk][bn + 1]);
            SPLIT_STORE(v.z, Bh[bk][bn + 2], Bl[bk][bn + 2]);
            SPLIT_STORE(v.w, Bh[bk][bn + 3], Bl[bk][bn + 3]);
        }
        __syncthreads();
#pragma unroll
        for (int kk = 0; kk < KC; kk += 8) {
            unsigned ah00, ah01, ah02, ah03, al00, al01, al02, al03;
            unsigned ah10, ah11, ah12, ah13, al10, al11, al12, al13;
            LOAD_AFRAG(ah00, ah01, ah02, ah03, al00, al01, al02, al03, wr + g, kk);
            LOAD_AFRAG(ah10, ah11, ah12, ah13, al10, al11, al12, al13, wr + 16 + g, kk);
            unsigned bh00, bh01, bl00, bl01;
            unsigned bh10, bh11, bl10, bl11;
            unsigned bh20, bh21, bl20, bl21;
            unsigned bh30, bh31, bl30, bl31;
            LOAD_BFRAG(bh00, bh01, bl00, bl01, wc + 0 + g, kk);
            LOAD_BFRAG(bh10, bh11, bl10, bl11, wc + 8 + g, kk);
            LOAD_BFRAG(bh20, bh21, bl20, bl21, wc + 16 + g, kk);
            LOAD_BFRAG(bh30, bh31, bl30, bl31, wc + 24 + g, kk);

            MMA3(c000,c001,c002,c003, ah00,ah01,ah02,ah03, al00,al01,al02,al03, bh00,bh01, bl00,bl01);
            MMA3(c010,c011,c012,c013, ah00,ah01,ah02,ah03, al00,al01,al02,al03, bh10,bh11, bl10,bl11);
            MMA3(c020,c021,c022,c023, ah00,ah01,ah02,ah03, al00,al01,al02,al03, bh20,bh21, bl20,bl21);
            MMA3(c030,c031,c032,c033, ah00,ah01,ah02,ah03, al00,al01,al02,al03, bh30,bh31, bl30,bl31);
            MMA3(c100,c101,c102,c103, ah10,ah11,ah12,ah13, al10,al11,al12,al13, bh00,bh01, bl00,bl01);
            MMA3(c110,c111,c112,c113, ah10,ah11,ah12,ah13, al10,al11,al12,al13, bh10,bh11, bl10,bl11);
            MMA3(c120,c121,c122,c123, ah10,ah11,ah12,ah13, al10,al11,al12,al13, bh20,bh21, bl20,bl21);
            MMA3(c130,c131,c132,c133, ah10,ah11,ah12,ah13, al10,al11,al12,al13, bh30,bh31, bl30,bl31);
        }
        __syncthreads();
    }

#define STORE_TILE(c0,c1,c2,c3, mi, ni)                                        \
    do { int _r = row0 + wr + (mi) * 16 + g;                                   \
         int _c = wc + (ni) * 8 + 2 * tg;                                      \
         if (_r < n) { C[(size_t)_r * 64 + _c] = c0;                           \
                       C[(size_t)_r * 64 + _c + 1] = c1; }                     \
         if (_r + 8 < n) { C[(size_t)(_r + 8) * 64 + _c] = c2;                 \
                           C[(size_t)(_r + 8) * 64 + _c + 1] = c3; } } while (0)

    STORE_TILE(c000,c001,c002,c003, 0, 0);
    STORE_TILE(c010,c011,c012,c013, 0, 1);
    STORE_TILE(c020,c021,c022,c023, 0, 2);
    STORE_TILE(c030,c031,c032,c033, 0, 3);
    STORE_TILE(c100,c101,c102,c103, 1, 0);
    STORE_TILE(c110,c111,c112,c113, 1, 1);
    STORE_TILE(c120,c121,c122,c123, 1, 2);
    STORE_TILE(c130,c131,c132,c133, 1, 3);
#undef STORE_TILE

    // ---- fused attention-coefficient epilogue ----
    {
        const float* asp = (MODE == 0) ? asA : (wc == 0 ? asA : asB);
        const float* adp = (MODE == 0) ? adA : (wc == 0 ? adA : adB);
        const int cmask = (MODE == 0) ? 63 : 31;
        const int slot = (MODE == 1 && wc == 32) ? 2 : 0;

        float s0 = 0.f, d0 = 0.f, s1 = 0.f, d1 = 0.f;
        float s2 = 0.f, d2 = 0.f, s3 = 0.f, d3 = 0.f;

#define EPI(cA0,cA1,cA2,cA3, cB0,cB1,cB2,cB3, ni)                              \
    do { int _c = (wc + (ni) * 8 + 2 * tg) & cmask;                            \
         float _a0 = __ldg(asp + _c), _a1 = __ldg(asp + _c + 1);               \
         float _b0 = __ldg(adp + _c), _b1 = __ldg(adp + _c + 1);               \
         s0 += cA0 * _a0 + cA1 * _a1;  d0 += cA0 * _b0 + cA1 * _b1;            \
         s1 += cA2 * _a0 + cA3 * _a1;  d1 += cA2 * _b0 + cA3 * _b1;            \
         s2 += cB0 * _a0 + cB1 * _a1;  d2 += cB0 * _b0 + cB1 * _b1;            \
         s3 += cB2 * _a0 + cB3 * _a1;  d3 += cB2 * _b0 + cB3 * _b1; } while (0)

        EPI(c000,c001,c002,c003, c100,c101,c102,c103, 0);
        EPI(c010,c011,c012,c013, c110,c111,c112,c113, 1);
        EPI(c020,c021,c022,c023, c120,c121,c122,c123, 2);
        EPI(c030,c031,c032,c033, c130,c131,c132,c133, 3);
#undef EPI

#pragma unroll
        for (int o = 1; o < 4; o <<= 1) {
            s0 += __shfl_xor_sync(0xffffffffu, s0, o);
            d0 += __shfl_xor_sync(0xffffffffu, d0, o);
            s1 += __shfl_xor_sync(0xffffffffu, s1, o);
            d1 += __shfl_xor_sync(0xffffffffu, d1, o);
            s2 += __shfl_xor_sync(0xffffffffu, s2, o);
            d2 += __shfl_xor_sync(0xffffffffu, d2, o);
            s3 += __shfl_xor_sync(0xffffffffu, s3, o);
            d3 += __shfl_xor_sync(0xffffffffu, d3, o);
        }
        if (tg == 0) {
            atomicAdd(&sred[wr + g][slot],          s0);
            atomicAdd(&sred[wr + g][slot + 1],      d0);
            atomicAdd(&sred[wr + 8 + g][slot],      s1);
            atomicAdd(&sred[wr + 8 + g][slot + 1],  d1);
            atomicAdd(&sred[wr + 16 + g][slot],     s2);
            atomicAdd(&sred[wr + 16 + g][slot + 1], d2);
            atomicAdd(&sred[wr + 24 + g][slot],     s3);
            atomicAdd(&sred[wr + 24 + g][slot + 1], d3);
        }
        __syncthreads();
        if (t < 128) {
            int r = row0 + t;
            if (r < n) {
                if (MODE == 0) {
                    g_es1[r] = sred[t][0];
                    g_ed1[r] = sred[t][1];
                } else {
                    g_es23[r] = make_float2(sred[t][0], sred[t][2]);
                    g_ed23[r] = make_float2(sred[t][1], sred[t][3]);
                }
            }
        }
    }
}

// ---------------------------------------------------------------------------
// CSR build
__global__ void k_hist(const int* __restrict__ dst, int e) {
    int i = (blockIdx.x * blockDim.x + threadIdx.x) * 4;
    if (i + 3 < e) {
        int4 d = *(const int4*)(dst + i);
        atomicAdd(&g_cnt[d.x], 1);
        atomicAdd(&g_cnt[d.y], 1);
        atomicAdd(&g_cnt[d.z], 1);
        atomicAdd(&g_cnt[d.w], 1);
    } else {
        for (int j = i; j < e; j++) atomicAdd(&g_cnt[dst[j]], 1);
    }
}

__global__ void k_scan1(int n) {
    __shared__ int wsum[8];
    int t = threadIdx.x, b = blockIdx.x;
    int base = b * 1024 + t * 4;
    int v0 = 0, v1 = 0, v2 = 0, v3 = 0;
    if (base + 3 < n) {
        int4 v = *(const int4*)&g_cnt[base];
        v0 = v.x; v1 = v.y; v2 = v.z; v3 = v.w;
        *(int4*)&g_cnt[base] = make_int4(0, 0, 0, 0);
    } else {
        if (base < n)     { v0 = g_cnt[base];     g_cnt[base]     = 0; }
        if (base + 1 < n) { v1 = g_cnt[base + 1]; g_cnt[base + 1] = 0; }
        if (base + 2 < n) { v2 = g_cnt[base + 2]; g_cnt[base + 2] = 0; }
        if (base + 3 < n) { v3 = g_cnt[base + 3]; g_cnt[base + 3] = 0; }
    }
    int s1 = v0 + v1, s2 = s1 + v2, s3 = s2 + v3;
    int lane = t & 31, w = t >> 5;
    int xs = s3;
#pragma unroll
    for (int o = 1; o < 32; o <<= 1) {
        int y = __shfl_up_sync(0xffffffffu, xs, o);
        if (lane >= o) xs += y;
    }
    if (lane == 31) wsum[w] = xs;
    __syncthreads();
    if (t < 8) {
        int v = wsum[t];
#pragma unroll
        for (int o = 1; o < 8; o <<= 1) {
            int y = __shfl_up_sync(0xffu, v, o);
            if (t >= o) v += y;
        }
        wsum[t] = v;
    }
    __syncthreads();
    int off = (w ? wsum[w - 1] : 0) + (xs - s3);
    if (base < n)     g_rowptr[base]     = off;
    if (base + 1 < n) g_rowptr[base + 1] = off + v0;
    if (base + 2 < n) g_rowptr[base + 2] = off + s1;
    if (base + 3 < n) g_rowptr[base + 3] = off + s2;
    if (t == 255) g_bsum[b] = off + s3;
}

__global__ void k_scan23(int n, int nb) {
    __shared__ int sh[65];
    int t = threadIdx.x;
    if (t == 0) {
        int run = 0;
        for (int j = 0; j < nb; j++) { int v = g_bsum[j]; sh[j] = run; run += v; }
        sh[nb] = run;
    }
    __syncthreads();
    int i = blockIdx.x * blockDim.x + t;
    if (i < n) {
        int v = g_rowptr[i] + sh[i >> 10];
        g_rowptr[i] = v;
        g_fill[i] = v;
    }
    if (i == 0) g_rowptr[n] = sh[nb];
}

__global__ void k_scatter(const int* __restrict__ src, const int* __restrict__ dst, int e) {
    int i = (blockIdx.x * blockDim.x + threadIdx.x) * 8;
    if (i + 7 < e) {
        int4 s0 = *(const int4*)(src + i);
        int4 s1 = *(const int4*)(src + i + 4);
        int4 d0 = *(const int4*)(dst + i);
        int4 d1 = *(const int4*)(dst + i + 4);
        int p0 = atomicAdd(&g_fill[d0.x], 1);
        int p1 = atomicAdd(&g_fill[d0.y], 1);
        int p2 = atomicAdd(&g_fill[d0.z], 1);
        int p3 = atomicAdd(&g_fill[d0.w], 1);
        int p4 = atomicAdd(&g_fill[d1.x], 1);
        int p5 = atomicAdd(&g_fill[d1.y], 1);
        int p6 = atomicAdd(&g_fill[d1.z], 1);
        int p7 = atomicAdd(&g_fill[d1.w], 1);
        g_col[p0] = s0.x; g_col[p1] = s0.y; g_col[p2] = s0.z; g_col[p3] = s0.w;
        g_col[p4] = s1.x; g_col[p5] = s1.y; g_col[p6] = s1.z; g_col[p7] = s1.w;
    } else {
        for (int j = i; j < e; j++)
            g_col[atomicAdd(&g_fill[dst[j]], 1)] = src[j];
    }
}

// ---------------------------------------------------------------------------
__device__ __forceinline__ float lrelu(float x) { return x >= 0.f ? x : 0.2f * x; }

// layer-1 aggregation: warp per dst; deg<=32 keeps p/col in registers and
// broadcasts via shuffle (no g_p round-trip). deg>32 falls back to scratch.
__global__ void k_agg1(const float* __restrict__ b1, int n) {
    int w = (blockIdx.x * blockDim.x + threadIdx.x) >> 5;
    int lane = threadIdx.x & 31;
    if (w >= n) return;
    int beg = g_rowptr[w], end = g_rowptr[w + 1];
    int deg = end - beg;
    float edn = g_ed1[w];
    const float2* hp = (const float2*)g_h1p;

    float ax0 = 0.f, ay0 = 0.f, ax1 = 0.f, ay1 = 0.f;
    float inv;

    if (deg <= 32) {
        float preg = 0.f;
        int creg = 0;
        if (lane < deg) {
            creg = g_col[beg + lane];
            preg = __expf(lrelu(g_es1[creg] + edn));
        }
        float S = preg;
#pragma unroll
        for (int o = 16; o; o >>= 1) S += __shfl_xor_sync(0xffffffffu, S, o);
        inv = 1.f / (S + 1e-16f);

        int j = 0;
        for (; j + 2 <= deg; j += 2) {
            float p0 = __shfl_sync(0xffffffffu, preg, j);
            float p1 = __shfl_sync(0xffffffffu, preg, j + 1);
            int s0 = __shfl_sync(0xffffffffu, creg, j);
            int s1 = __shfl_sync(0xffffffffu, creg, j + 1);
            float2 h0 = hp[(size_t)s0 * 32 + lane];
            float2 h1 = hp[(size_t)s1 * 32 + lane];
            ax0 += p0 * h0.x; ay0 += p0 * h0.y;
            ax1 += p1 * h1.x; ay1 += p1 * h1.y;
        }
        if (j < deg) {
            float p0 = __shfl_sync(0xffffffffu, preg, j);
            int s0 = __shfl_sync(0xffffffffu, creg, j);
            float2 h0 = hp[(size_t)s0 * 32 + lane];
            ax0 += p0 * h0.x; ay0 += p0 * h0.y;
        }
    } else {
        float S = 0.f;
        for (int i = beg + lane; i < end; i += 32) {
            float p = __expf(lrelu(g_es1[g_col[i]] + edn));
            g_p[i] = p;
            S += p;
        }
#pragma unroll
        for (int o = 16; o; o >>= 1) S += __shfl_xor_sync(0xffffffffu, S, o);
        inv = 1.f / (S + 1e-16f);
        __syncwarp();

        int i = beg;
        for (; i + 2 <= end; i += 2) {
            float p0 = g_p[i], p1 = g_p[i + 1];
            int s0 = g_col[i], s1 = g_col[i + 1];
            float2 h0 = hp[(size_t)s0 * 32 + lane];
            float2 h1 = hp[(size_t)s1 * 32 + lane];
            ax0 += p0 * h0.x; ay0 += p0 * h0.y;
            ax1 += p1 * h1.x; ay1 += p1 * h1.y;
        }
        if (i < end) {
            float p0 = g_p[i];
            float2 h0 = hp[(size_t)g_col[i] * 32 + lane];
            ax0 += p0 * h0.x; ay0 += p0 * h0.y;
        }
    }

    float ox = (ax0 + ax1) * inv + __ldg(b1 + 2 * lane);
    float oy = (ay0 + ay1) * inv + __ldg(b1 + 2 * lane + 1);
    ox = ox > 0.f ? ox : expm1f(ox);
    oy = oy > 0.f ? oy : expm1f(oy);
    ((float2*)g_h1)[(size_t)w * 32 + lane] = make_float2(ox, oy);
}

// layers 2 (mean) + 3 (var, self-loop) fused; shuffle path for deg<=32.
__global__ void k_agg23(const float* __restrict__ b2, const float* __restrict__ b3,
                        const float* __restrict__ Wl, const float* __restrict__ bl,
                        float* __restrict__ out_mean, float* __restrict__ out_var,
                        int n) {
    __shared__ float Wls[1024];
    for (int i = threadIdx.x; i < 1024; i += blockDim.x) Wls[i] = Wl[i];
    __syncthreads();

    int w = (blockIdx.x * blockDim.x + threadIdx.x) >> 5;
    int lane = threadIdx.x & 31;
    if (w >= n) return;
    int beg = g_rowptr[w], end = g_rowptr[w + 1];
    int deg = end - beg;
    float2 edn = g_ed23[w];

    float aM0 = 0.f, aV0 = 0.f, aM1 = 0.f, aV1 = 0.f;
    float inv2, inv3, pself;

    if (deg <= 32) {
        float p2reg = 0.f, p3reg = 0.f;
        int creg = 0;
        if (lane < deg) {
            creg = g_col[beg + lane];
            float2 es = g_es23[creg];
            p2reg = __expf(lrelu(es.x + edn.x));
            p3reg = __expf(lrelu(es.y + edn.y));
        }
        float S2 = p2reg, S3 = p3reg;
#pragma unroll
        for (int o = 16; o; o >>= 1) {
            S2 += __shfl_xor_sync(0xffffffffu, S2, o);
            S3 += __shfl_xor_sync(0xffffffffu, S3, o);
        }
        inv2 = 1.f / (S2 + 1e-16f);
        pself = __expf(lrelu(g_es23[w].y + edn.y));
        S3 += pself;
        inv3 = 1.f / (S3 + 1e-16f);
        if (lane == 0) g_dai[w] = make_float2(edn.x, inv2);

        int j = 0;
        for (; j + 2 <= deg; j += 2) {
            float q20 = __shfl_sync(0xffffffffu, p2reg, j);
            float q30 = __shfl_sync(0xffffffffu, p3reg, j);
            float q21 = __shfl_sync(0xffffffffu, p2reg, j + 1);
            float q31 = __shfl_sync(0xffffffffu, p3reg, j + 1);
            int s0 = __shfl_sync(0xffffffffu, creg, j);
            int s1 = __shfl_sync(0xffffffffu, creg, j + 1);
            aM0 += q20 * g_h23[(size_t)s0 * 64 + lane];
            aV0 += q30 * g_h23[(size_t)s0 * 64 + 32 + lane];
            aM1 += q21 * g_h23[(size_t)s1 * 64 + lane];
            aV1 += q31 * g_h23[(size_t)s1 * 64 + 32 + lane];
        }
        if (j < deg) {
            float q20 = __shfl_sync(0xffffffffu, p2reg, j);
            float q30 = __shfl_sync(0xffffffffu, p3reg, j);
            int s0 = __shfl_sync(0xffffffffu, creg, j);
            aM0 += q20 * g_h23[(size_t)s0 * 64 + lane];
            aV0 += q30 * g_h23[(size_t)s0 * 64 + 32 + lane];
        }
    } else {
        float S2 = 0.f, S3 = 0.f;
        for (int i = beg + lane; i < end; i += 32) {
            float2 es = g_es23[g_col[i]];
            float p2 = __expf(lrelu(es.x + edn.x));
            float p3 = __expf(lrelu(es.y + edn.y));
            g_pp[i] = make_float2(p2, p3);
            S2 += p2;
            S3 += p3;
        }
#pragma unroll
        for (int o = 16; o; o >>= 1) {
            S2 += __shfl_xor_sync(0xffffffffu, S2, o);
            S3 += __shfl_xor_sync(0xffffffffu, S3, o);
        }
        inv2 = 1.f / (S2 + 1e-16f);
        pself = __expf(lrelu(g_es23[w].y + edn.y));
        S3 += pself;
        inv3 = 1.f / (S3 + 1e-16f);
        if (lane == 0) g_dai[w] = make_float2(edn.x, inv2);
        __syncwarp();

        int i = beg;
        for (; i + 2 <= end; i += 2) {
            int s0 = g_col[i], s1 = g_col[i + 1];
            float2 pp0 = g_pp[i], pp1 = g_pp[i + 1];
            aM0 += pp0.x * g_h23[(size_t)s0 * 64 + lane];
            aV0 += pp0.y * g_h23[(size_t)s0 * 64 + 32 + lane];
            aM1 += pp1.x * g_h23[(size_t)s1 * 64 + lane];
            aV1 += pp1.y * g_h23[(size_t)s1 * 64 + 32 + lane];
        }
        if (i < end) {
            int s0 = g_col[i];
            float2 pp0 = g_pp[i];
            aM0 += pp0.x * g_h23[(size_t)s0 * 64 + lane];
            aV0 += pp0.y * g_h23[(size_t)s0 * 64 + 32 + lane];
        }
    }

    float accM = aM0 + aM1, accV = aV0 + aV1;
    accV = (accV + pself * g_h23[(size_t)w * 64 + 32 + lane]) * inv3 + __ldg(b3 + lane);
    out_var[(size_t)w * 32 + lane] = accV;

    float mp = accM * inv2 + __ldg(b2 + lane);
    mp = fmaxf(mp, 0.f);
    float acc = 0.f;
#pragma unroll
    for (int f = 0; f < 32; f++) {
        float v = __shfl_sync(0xffffffffu, mp, f);
        acc += v * Wls[f * 32 + lane];
    }
    out_mean[(size_t)w * 32 + lane] = acc + __ldg(bl + lane);
}

// edge-parallel alpha: 2 random gathers/edge, coalesced write.
__global__ void k_alpha(const int* __restrict__ src, const int* __restrict__ dst,
                        float* __restrict__ out_alpha, int e) {
    int i = (blockIdx.x * blockDim.x + threadIdx.x) * 4;
    if (i + 3 < e) {
        int4 s = *(const int4*)(src + i);
        int4 d = *(const int4*)(dst + i);
        float2 a0 = g_dai[d.x], a1 = g_dai[d.y], a2 = g_dai[d.z], a3 = g_dai[d.w];
        float e0 = g_es23[s.x].x, e1 = g_es23[s.y].x;
        float e2 = g_es23[s.z].x, e3 = g_es23[s.w].x;
        float4 r;
        r.x = __expf(lrelu(e0 + a0.x)) * a0.y;
        r.y = __expf(lrelu(e1 + a1.x)) * a1.y;
        r.z = __expf(lrelu(e2 + a2.x)) * a2.y;
        r.w = __expf(lrelu(e3 + a3.x)) * a3.y;
        *(float4*)(out_alpha + i) = r;
    } else {
        for (int j = i; j < e; j++) {
            float2 a = g_dai[dst[j]];
            out_alpha[j] = __expf(lrelu(g_es23[src[j]].x + a.x)) * a.y;
        }
    }
}

// ---------------------------------------------------------------------------
extern "C" void kernel_launch(void* const* d_in, const int* in_sizes, int n_in,
                              void* d_out, int out_size) {
    const float* x   = (const float*)d_in[0];
    const int*   ei  = (const int*)  d_in[1];
    const float* W1  = (const float*)d_in[2];
    const float* a1s = (const float*)d_in[3];
    const float* a1d = (const float*)d_in[4];
    const float* b1  = (const float*)d_in[5];
    const float* W2  = (const float*)d_in[6];
    const float* a2s = (const float*)d_in[7];
    const float* a2d = (const float*)d_in[8];
    const float* b2  = (const float*)d_in[9];
    const float* W3  = (const float*)d_in[10];
    const float* a3s = (const float*)d_in[11];
    const float* a3d = (const float*)d_in[12];
    const float* b3  = (const float*)d_in[13];
    const float* Wl  = (const float*)d_in[14];
    const float* bl  = (const float*)d_in[15];

    const int n = in_sizes[0] / 256;
    const int e = in_sizes[1] / 2;
    const int* src = ei;
    const int* dst = ei + e;

    float* out_mean  = (float*)d_out;
    float* out_var   = out_mean + (size_t)n * 32;
    float* out_alpha = out_var + (size_t)n * 32;

    const int TB = 256;
    int gridN  = (n + TB - 1) / TB;
    int gridE4 = ((e + 3) / 4 + TB - 1) / TB;
    int gridE8 = ((e + 7) / 8 + TB - 1) / TB;
    int gridM  = (n + 127) / 128;
    int gridW  = (n * 32 + TB - 1) / TB;
    int nb     = (n + 1023) / 1024;

    static cudaStream_t s_b = nullptr;
    static cudaEvent_t ev_fork = nullptr, ev_join = nullptr;
    if (s_b == nullptr) {
        cudaStreamCreateWithFlags(&s_b, cudaStreamNonBlocking);
        cudaEventCreateWithFlags(&ev_fork, cudaEventDisableTiming);
        cudaEventCreateWithFlags(&ev_join, cudaEventDisableTiming);
    }

    // fork: CSR chain on s_b, gemm1 on default stream
    cudaEventRecord(ev_fork, 0);
    cudaStreamWaitEvent(s_b, ev_fork, 0);
    k_hist<<<gridE4, TB, 0, s_b>>>(dst, e);
    k_scan1<<<nb, TB, 0, s_b>>>(n);
    k_scan23<<<gridN, TB, 0, s_b>>>(n, nb);
    k_scatter<<<gridE8, TB, 0, s_b>>>(src, dst, e);
    cudaEventRecord(ev_join, s_b);

    k_gemm_tc<0><<<gridM, TB>>>(x, W1, nullptr, a1s, a1d, a1s, a1d, n);

    // join: everything below needs both CSR and gemm1 results
    cudaStreamWaitEvent(0, ev_join, 0);
    k_agg1<<<gridW, TB>>>(b1, n);
    k_gemm_tc<1><<<gridM, TB>>>(nullptr, W2, W3, a2s, a2d, a3s, a3d, n);
    k_agg23<<<gridW, TB>>>(b2, b3, Wl, bl, out_mean, out_var, n);
    k_alpha<<<gridE4, TB>>>(src, dst, out_alpha, e);
}

// round 12
// speedup vs baseline: 1.0590x; 1.0590x over previous
#include <cuda_runtime.h>
#include <cuda_fp16.h>
#include <math.h>
#include <stdint.h>

// ---------------------------------------------------------------------------
// GAT_linear_negbin: 3x GATConv (single head) + linear head.
// Round 12: revert shuffle-agg (regressed) to round-10 scratch path; store
// gather-only feature arrays (h1p, h23) in fp16 — halves agg L2 traffic.
// h23 interleaved (h2[c],h3[c]) as half2 -> one 4B/lane read per edge.
// ---------------------------------------------------------------------------

#define NMAX 50000
#define EMAX 800000

__device__ __half  g_h1ph[NMAX * 64];  // x@W1, fp16 (gathered by agg1 only)
__device__ float   g_h1 [NMAX * 64];   // post softmax-agg + elu (fp32, gemm23 A)
__device__ __half  g_h23h[NMAX * 64];  // interleaved: [2c]=h2[c], [2c+1]=h3[c]
__device__ float   g_es1[NMAX], g_ed1[NMAX];
__device__ float2  g_es23[NMAX];       // (es2, es3)
__device__ float2  g_ed23[NMAX];       // (ed2, ed3)
__device__ float2  g_dai[NMAX];        // (ed2, inv2) for edge-parallel alpha
__device__ float   g_p  [EMAX];
__device__ float2  g_pp [EMAX];
__device__ int     g_cnt[NMAX];        // zero at load; self-zeroed by scan1
__device__ int     g_rowptr[NMAX + 1];
__device__ int     g_fill[NMAX];
__device__ int     g_col[EMAX];
__device__ int     g_bsum[64];

// ---------------------------------------------------------------------------
__device__ __forceinline__ unsigned f2tf(float f) {
    unsigned r;
    asm("cvt.rna.tf32.f32 %0, %1;" : "=r"(r) : "f"(f));
    return r;
}

#define MMA(c0,c1,c2,c3,a0,a1,a2,a3,b0,b1)                                     \
    asm volatile(                                                              \
        "mma.sync.aligned.m16n8k8.row.col.f32.tf32.tf32.f32 "                  \
        "{%0,%1,%2,%3}, {%4,%5,%6,%7}, {%8,%9}, {%0,%1,%2,%3};"                \
        : "+f"(c0), "+f"(c1), "+f"(c2), "+f"(c3)                               \
        : "r"(a0), "r"(a1), "r"(a2), "r"(a3), "r"(b0), "r"(b1))

#define SPLIT_STORE(val, HI, LO)                                               \
    do { unsigned _hb = f2tf(val); float _hf = __uint_as_float(_hb);           \
         (HI) = _hf; (LO) = __uint_as_float(f2tf((val) - _hf)); } while (0)

#define LOAD_AFRAG(h0,h1,h2,h3,l0,l1,l2,l3,r0,kk)                              \
    do { h0 = __float_as_uint(Ah[(r0)][(kk) + tg]);                            \
         h1 = __float_as_uint(Ah[(r0) + 8][(kk) + tg]);                        \
         h2 = __float_as_uint(Ah[(r0)][(kk) + tg + 4]);                        \
         h3 = __float_as_uint(Ah[(r0) + 8][(kk) + tg + 4]);                    \
         l0 = __float_as_uint(Al[(r0)][(kk) + tg]);                            \
         l1 = __float_as_uint(Al[(r0) + 8][(kk) + tg]);                        \
         l2 = __float_as_uint(Al[(r0)][(kk) + tg + 4]);                        \
         l3 = __float_as_uint(Al[(r0) + 8][(kk) + tg + 4]); } while (0)

#define LOAD_BFRAG(h0,h1,l0,l1,c0,kk)                                          \
    do { h0 = __float_as_uint(Bh[(kk) + tg][(c0)]);                            \
         h1 = __float_as_uint(Bh[(kk) + tg + 4][(c0)]);                        \
         l0 = __float_as_uint(Bl[(kk) + tg][(c0)]);                            \
         l1 = __float_as_uint(Bl[(kk) + tg + 4][(c0)]); } while (0)

#define MMA3(c0,c1,c2,c3,ah0,ah1,ah2,ah3,al0,al1,al2,al3,bh0,bh1,bl0,bl1)      \
    do { MMA(c0,c1,c2,c3, ah0,ah1,ah2,ah3, bh0,bh1);                           \
         MMA(c0,c1,c2,c3, ah0,ah1,ah2,ah3, bl0,bl1);                           \
         MMA(c0,c1,c2,c3, al0,al1,al2,al3, bh0,bh1); } while (0)

// 3xTF32 TC GEMM + fused attention-coefficient epilogue.
// MODE 0: Aarg[n,256]@B1[256,64] -> g_h1ph (fp16); es1/ed1 from fp32 accum.
// MODE 1: g_h1[n,64]@[B1|B2]     -> g_h23h (fp16, interleaved); es23/ed23.
template <int MODE>
__global__ __launch_bounds__(256) void k_gemm_tc(const float* __restrict__ Aarg,
                                                 const float* __restrict__ B1,
                                                 const float* __restrict__ B2,
                                                 const float* __restrict__ asA,
                                                 const float* __restrict__ adA,
                                                 const float* __restrict__ asB,
                                                 const float* __restrict__ adB,
                                                 int n) {
    constexpr int K = (MODE == 0) ? 256 : 64;
    constexpr int KC = 16;
    const float* A = (MODE == 0) ? Aarg : g_h1;
    __half* Ch = (MODE == 0) ? g_h1ph : g_h23h;

    __shared__ float Ah[128][KC + 2];
    __shared__ float Al[128][KC + 2];
    __shared__ float Bh[KC][68];
    __shared__ float Bl[KC][68];
    __shared__ float sred[128][4];
    const int t = threadIdx.x;
    const int lane = t & 31, warp = t >> 5;
    const int wr = (warp & 3) * 32, wc = (warp >> 2) * 32;
    const int row0 = blockIdx.x * 128;
    const int g = lane >> 2, tg = lane & 3;

    {
        float* f = &sred[0][0];
        for (int i = t; i < 512; i += 256) f[i] = 0.f;
    }

    float c000 = 0.f, c001 = 0.f, c002 = 0.f, c003 = 0.f;
    float c010 = 0.f, c011 = 0.f, c012 = 0.f, c013 = 0.f;
    float c020 = 0.f, c021 = 0.f, c022 = 0.f, c023 = 0.f;
    float c030 = 0.f, c031 = 0.f, c032 = 0.f, c033 = 0.f;
    float c100 = 0.f, c101 = 0.f, c102 = 0.f, c103 = 0.f;
    float c110 = 0.f, c111 = 0.f, c112 = 0.f, c113 = 0.f;
    float c120 = 0.f, c121 = 0.f, c122 = 0.f, c123 = 0.f;
    float c130 = 0.f, c131 = 0.f, c132 = 0.f, c133 = 0.f;

    for (int kc = 0; kc < K; kc += KC) {
        {
            int ar = t >> 1, ak = (t & 1) * 8;
            float4 v0 = make_float4(0.f, 0.f, 0.f, 0.f), v1 = v0;
            if (row0 + ar < n) {
                const float* ap = A + (size_t)(row0 + ar) * K + kc + ak;
                v0 = *(const float4*)ap;
                v1 = *(const float4*)(ap + 4);
            }
            SPLIT_STORE(v0.x, Ah[ar][ak + 0], Al[ar][ak + 0]);
            SPLIT_STORE(v0.y, Ah[ar][ak + 1], Al[ar][ak + 1]);
            SPLIT_STORE(v0.z, Ah[ar][ak + 2], Al[ar][ak + 2]);
            SPLIT_STORE(v0.w, Ah[ar][ak + 3], Al[ar][ak + 3]);
            SPLIT_STORE(v1.x, Ah[ar][ak + 4], Al[ar][ak + 4]);
            SPLIT_STORE(v1.y, Ah[ar][ak + 5], Al[ar][ak + 5]);
            SPLIT_STORE(v1.z, Ah[ar][ak + 6], Al[ar][ak + 6]);
            SPLIT_STORE(v1.w, Ah[ar][ak + 7], Al[ar][ak + 7]);
        }
        {
            int bk = t >> 4, bn = (t & 15) * 4;
            const float* bp;
            if (MODE == 0) bp = B1 + (size_t)(kc + bk) * 64 + bn;
            else bp = (bn < 32) ? B1 + (size_t)(kc + bk) * 32 + bn
                                : B2 + (size_t)(kc + bk) * 32 + (bn - 32);
            float4 v = *(const float4*)bp;
            SPLIT_STORE(v.x, Bh[bk][bn + 0], Bl[bk][bn + 0]);
            SPLIT_STORE(v.y, Bh[bk][bn + 1], Bl[bk][bn + 1]);
            SPLIT_STORE(v.z, Bh[bk][bn + 2], Bl[bk][bn + 2]);
            SPLIT_STORE(v.w, Bh[bk][bn + 3], Bl[bk][bn + 3]);
        }
        __syncthreads();
#pragma unroll
        for (int kk = 0; kk < KC; kk += 8) {
            unsigned ah00, ah01, ah02, ah03, al00, al01, al02, al03;
            unsigned ah10, ah11, ah12, ah13, al10, al11, al12, al13;
            LOAD_AFRAG(ah00, ah01, ah02, ah03, al00, al01, al02, al03, wr + g, kk);
            LOAD_AFRAG(ah10, ah11, ah12, ah13, al10, al11, al12, al13, wr + 16 + g, kk);
            unsigned bh00, bh01, bl00, bl01;
            unsigned bh10, bh11, bl10, bl11;
            unsigned bh20, bh21, bl20, bl21;
            unsigned bh30, bh31, bl30, bl31;
            LOAD_BFRAG(bh00, bh01, bl00, bl01, wc + 0 + g, kk);
            LOAD_BFRAG(bh10, bh11, bl10, bl11, wc + 8 + g, kk);
            LOAD_BFRAG(bh20, bh21, bl20, bl21, wc + 16 + g, kk);
            LOAD_BFRAG(bh30, bh31, bl30, bl31, wc + 24 + g, kk);

            MMA3(c000,c001,c002,c003, ah00,ah01,ah02,ah03, al00,al01,al02,al03, bh00,bh01, bl00,bl01);
            MMA3(c010,c011,c012,c013, ah00,ah01,ah02,ah03, al00,al01,al02,al03, bh10,bh11, bl10,bl11);
            MMA3(c020,c021,c022,c023, ah00,ah01,ah02,ah03, al00,al01,al02,al03, bh20,bh21, bl20,bl21);
            MMA3(c030,c031,c032,c033, ah00,ah01,ah02,ah03, al00,al01,al02,al03, bh30,bh31, bl30,bl31);
            MMA3(c100,c101,c102,c103, ah10,ah11,ah12,ah13, al10,al11,al12,al13, bh00,bh01, bl00,bl01);
            MMA3(c110,c111,c112,c113, ah10,ah11,ah12,ah13, al10,al11,al12,al13, bh10,bh11, bl10,bl11);
            MMA3(c120,c121,c122,c123, ah10,ah11,ah12,ah13, al10,al11,al12,al13, bh20,bh21, bl20,bl21);
            MMA3(c130,c131,c132,c133, ah10,ah11,ah12,ah13, al10,al11,al12,al13, bh30,bh31, bl30,bl31);
        }
        __syncthreads();
    }

    // ---- store C as fp16 ----
    // MODE 0: row-linear layout, cols (c, c+1) adjacent -> one half2 store.
    // MODE 1: interleaved layout, element (r,c) -> r*64 + 2*(c&31) + (c>=32).
#define STORE_TILE(c0,c1,c2,c3, mi, ni)                                        \
    do { int _r = row0 + wr + (mi) * 16 + g;                                   \
         int _c = wc + (ni) * 8 + 2 * tg;                                      \
         if (MODE == 0) {                                                      \
             if (_r < n)                                                       \
                 *(__half2*)(Ch + (size_t)_r * 64 + _c) =                      \
                     __floats2half2_rn(c0, c1);                                \
             if (_r + 8 < n)                                                   \
                 *(__half2*)(Ch + (size_t)(_r + 8) * 64 + _c) =                \
                     __floats2half2_rn(c2, c3);                                \
         } else {                                                              \
             int _b = (_c >= 32) ? 1 : 0;                                      \
             int _o = 2 * (_c & 31) + _b;                                      \
             if (_r < n) {                                                     \
                 Ch[(size_t)_r * 64 + _o]     = __float2half_rn(c0);           \
                 Ch[(size_t)_r * 64 + _o + 2] = __float2half_rn(c1);           \
             }                                                                 \
             if (_r + 8 < n) {                                                 \
                 Ch[(size_t)(_r + 8) * 64 + _o]     = __float2half_rn(c2);     \
                 Ch[(size_t)(_r + 8) * 64 + _o + 2] = __float2half_rn(c3);     \
             }                                                                 \
         } } while (0)

    STORE_TILE(c000,c001,c002,c003, 0, 0);
    STORE_TILE(c010,c011,c012,c013, 0, 1);
    STORE_TILE(c020,c021,c022,c023, 0, 2);
    STORE_TILE(c030,c031,c032,c033, 0, 3);
    STORE_TILE(c100,c101,c102,c103, 1, 0);
    STORE_TILE(c110,c111,c112,c113, 1, 1);
    STORE_TILE(c120,c121,c122,c123, 1, 2);
    STORE_TILE(c130,c131,c132,c133, 1, 3);
#undef STORE_TILE

    // ---- fused attention-coefficient epilogue (fp32 accumulators) ----
    {
        const float* asp = (MODE == 0) ? asA : (wc == 0 ? asA : asB);
        const float* adp = (MODE == 0) ? adA : (wc == 0 ? adA : adB);
        const int cmask = (MODE == 0) ? 63 : 31;
        const int slot = (MODE == 1 && wc == 32) ? 2 : 0;

        float s0 = 0.f, d0 = 0.f, s1 = 0.f, d1 = 0.f;
        float s2 = 0.f, d2 = 0.f, s3 = 0.f, d3 = 0.f;

#define EPI(cA0,cA1,cA2,cA3, cB0,cB1,cB2,cB3, ni)                              \
    do { int _c = (wc + (ni) * 8 + 2 * tg) & cmask;                            \
         float _a0 = __ldg(asp + _c), _a1 = __ldg(asp + _c + 1);               \
         float _b0 = __ldg(adp + _c), _b1 = __ldg(adp + _c + 1);               \
         s0 += cA0 * _a0 + cA1 * _a1;  d0 += cA0 * _b0 + cA1 * _b1;            \
         s1 += cA2 * _a0 + cA3 * _a1;  d1 += cA2 * _b0 + cA3 * _b1;            \
         s2 += cB0 * _a0 + cB1 * _a1;  d2 += cB0 * _b0 + cB1 * _b1;            \
         s3 += cB2 * _a0 + cB3 * _a1;  d3 += cB2 * _b0 + cB3 * _b1; } while (0)

        EPI(c000,c001,c002,c003, c100,c101,c102,c103, 0);
        EPI(c010,c011,c012,c013, c110,c111,c112,c113, 1);
        EPI(c020,c021,c022,c023, c120,c121,c122,c123, 2);
        EPI(c030,c031,c032,c033, c130,c131,c132,c133, 3);
#undef EPI

#pragma unroll
        for (int o = 1; o < 4; o <<= 1) {
            s0 += __shfl_xor_sync(0xffffffffu, s0, o);
            d0 += __shfl_xor_sync(0xffffffffu, d0, o);
            s1 += __shfl_xor_sync(0xffffffffu, s1, o);
            d1 += __shfl_xor_sync(0xffffffffu, d1, o);
            s2 += __shfl_xor_sync(0xffffffffu, s2, o);
            d2 += __shfl_xor_sync(0xffffffffu, d2, o);
            s3 += __shfl_xor_sync(0xffffffffu, s3, o);
            d3 += __shfl_xor_sync(0xffffffffu, d3, o);
        }
        if (tg == 0) {
            atomicAdd(&sred[wr + g][slot],          s0);
            atomicAdd(&sred[wr + g][slot + 1],      d0);
            atomicAdd(&sred[wr + 8 + g][slot],      s1);
            atomicAdd(&sred[wr + 8 + g][slot + 1],  d1);
            atomicAdd(&sred[wr + 16 + g][slot],     s2);
            atomicAdd(&sred[wr + 16 + g][slot + 1], d2);
            atomicAdd(&sred[wr + 24 + g][slot],     s3);
            atomicAdd(&sred[wr + 24 + g][slot + 1], d3);
        }
        __syncthreads();
        if (t < 128) {
            int r = row0 + t;
            if (r < n) {
                if (MODE == 0) {
                    g_es1[r] = sred[t][0];
                    g_ed1[r] = sred[t][1];
                } else {
                    g_es23[r] = make_float2(sred[t][0], sred[t][2]);
                    g_ed23[r] = make_float2(sred[t][1], sred[t][3]);
                }
            }
        }
    }
}

// ---------------------------------------------------------------------------
// CSR build
__global__ void k_hist(const int* __restrict__ dst, int e) {
    int i = (blockIdx.x * blockDim.x + threadIdx.x) * 4;
    if (i + 3 < e) {
        int4 d = *(const int4*)(dst + i);
        atomicAdd(&g_cnt[d.x], 1);
        atomicAdd(&g_cnt[d.y], 1);
        atomicAdd(&g_cnt[d.z], 1);
        atomicAdd(&g_cnt[d.w], 1);
    } else {
        for (int j = i; j < e; j++) atomicAdd(&g_cnt[dst[j]], 1);
    }
}

__global__ void k_scan1(int n) {
    __shared__ int wsum[8];
    int t = threadIdx.x, b = blockIdx.x;
    int base = b * 1024 + t * 4;
    int v0 = 0, v1 = 0, v2 = 0, v3 = 0;
    if (base + 3 < n) {
        int4 v = *(const int4*)&g_cnt[base];
        v0 = v.x; v1 = v.y; v2 = v.z; v3 = v.w;
        *(int4*)&g_cnt[base] = make_int4(0, 0, 0, 0);
    } else {
        if (base < n)     { v0 = g_cnt[base];     g_cnt[base]     = 0; }
        if (base + 1 < n) { v1 = g_cnt[base + 1]; g_cnt[base + 1] = 0; }
        if (base + 2 < n) { v2 = g_cnt[base + 2]; g_cnt[base + 2] = 0; }
        if (base + 3 < n) { v3 = g_cnt[base + 3]; g_cnt[base + 3] = 0; }
    }
    int s1 = v0 + v1, s2 = s1 + v2, s3 = s2 + v3;
    int lane = t & 31, w = t >> 5;
    int xs = s3;
#pragma unroll
    for (int o = 1; o < 32; o <<= 1) {
        int y = __shfl_up_sync(0xffffffffu, xs, o);
        if (lane >= o) xs += y;
    }
    if (lane == 31) wsum[w] = xs;
    __syncthreads();
    if (t < 8) {
        int v = wsum[t];
#pragma unroll
        for (int o = 1; o < 8; o <<= 1) {
            int y = __shfl_up_sync(0xffu, v, o);
            if (t >= o) v += y;
        }
        wsum[t] = v;
    }
    __syncthreads();
    int off = (w ? wsum[w - 1] : 0) + (xs - s3);
    if (base < n)     g_rowptr[base]     = off;
    if (base + 1 < n) g_rowptr[base + 1] = off + v0;
    if (base + 2 < n) g_rowptr[base + 2] = off + s1;
    if (base + 3 < n) g_rowptr[base + 3] = off + s2;
    if (t == 255) g_bsum[b] = off + s3;
}

__global__ void k_scan23(int n, int nb) {
    __shared__ int sh[65];
    int t = threadIdx.x;
    if (t == 0) {
        int run = 0;
        for (int j = 0; j < nb; j++) { int v = g_bsum[j]; sh[j] = run; run += v; }
        sh[nb] = run;
    }
    __syncthreads();
    int i = blockIdx.x * blockDim.x + t;
    if (i < n) {
        int v = g_rowptr[i] + sh[i >> 10];
        g_rowptr[i] = v;
        g_fill[i] = v;
    }
    if (i == 0) g_rowptr[n] = sh[nb];
}

__global__ void k_scatter(const int* __restrict__ src, const int* __restrict__ dst, int e) {
    int i = (blockIdx.x * blockDim.x + threadIdx.x) * 8;
    if (i + 7 < e) {
        int4 s0 = *(const int4*)(src + i);
        int4 s1 = *(const int4*)(src + i + 4);
        int4 d0 = *(const int4*)(dst + i);
        int4 d1 = *(const int4*)(dst + i + 4);
        int p0 = atomicAdd(&g_fill[d0.x], 1);
        int p1 = atomicAdd(&g_fill[d0.y], 1);
        int p2 = atomicAdd(&g_fill[d0.z], 1);
        int p3 = atomicAdd(&g_fill[d0.w], 1);
        int p4 = atomicAdd(&g_fill[d1.x], 1);
        int p5 = atomicAdd(&g_fill[d1.y], 1);
        int p6 = atomicAdd(&g_fill[d1.z], 1);
        int p7 = atomicAdd(&g_fill[d1.w], 1);
        g_col[p0] = s0.x; g_col[p1] = s0.y; g_col[p2] = s0.z; g_col[p3] = s0.w;
        g_col[p4] = s1.x; g_col[p5] = s1.y; g_col[p6] = s1.z; g_col[p7] = s1.w;
    } else {
        for (int j = i; j < e; j++)
            g_col[atomicAdd(&g_fill[dst[j]], 1)] = src[j];
    }
}

// ---------------------------------------------------------------------------
__device__ __forceinline__ float lrelu(float x) { return x >= 0.f ? x : 0.2f * x; }

// layer-1 aggregation: warp per dst; fp16 gathers (half2 = 2 feats per lane).
__global__ void k_agg1(const float* __restrict__ b1, int n) {
    int w = (blockIdx.x * blockDim.x + threadIdx.x) >> 5;
    int lane = threadIdx.x & 31;
    if (w >= n) return;
    int beg = g_rowptr[w], end = g_rowptr[w + 1];
    float edn = g_ed1[w];

    float S = 0.f;
    for (int i = beg + lane; i < end; i += 32) {
        float p = __expf(lrelu(g_es1[g_col[i]] + edn));
        g_p[i] = p;
        S += p;
    }
#pragma unroll
    for (int o = 16; o; o >>= 1) S += __shfl_xor_sync(0xffffffffu, S, o);
    float inv = 1.f / (S + 1e-16f);
    __syncwarp();

    float ax0 = 0.f, ay0 = 0.f, ax1 = 0.f, ay1 = 0.f;
    const __half2* hp = (const __half2*)g_h1ph;
    int i = beg;
    for (; i + 2 <= end; i += 2) {
        float p0 = g_p[i], p1 = g_p[i + 1];
        int s0 = g_col[i], s1 = g_col[i + 1];
        float2 h0 = __half22float2(hp[(size_t)s0 * 32 + lane]);
        float2 h1 = __half22float2(hp[(size_t)s1 * 32 + lane]);
        ax0 += p0 * h0.x; ay0 += p0 * h0.y;
        ax1 += p1 * h1.x; ay1 += p1 * h1.y;
    }
    if (i < end) {
        float p0 = g_p[i];
        float2 h0 = __half22float2(hp[(size_t)g_col[i] * 32 + lane]);
        ax0 += p0 * h0.x; ay0 += p0 * h0.y;
    }
    float ox = (ax0 + ax1) * inv + __ldg(b1 + 2 * lane);
    float oy = (ay0 + ay1) * inv + __ldg(b1 + 2 * lane + 1);
    ox = ox > 0.f ? ox : expm1f(ox);
    oy = oy > 0.f ? oy : expm1f(oy);
    ((float2*)g_h1)[(size_t)w * 32 + lane] = make_float2(ox, oy);
}

// layers 2 (mean) + 3 (var, self-loop) fused; interleaved fp16 gathers:
// one half2 per lane per edge = (h2[lane], h3[lane]).
__global__ void k_agg23(const float* __restrict__ b2, const float* __restrict__ b3,
                        const float* __restrict__ Wl, const float* __restrict__ bl,
                        float* __restrict__ out_mean, float* __restrict__ out_var,
                        int n) {
    __shared__ float Wls[1024];
    for (int i = threadIdx.x; i < 1024; i += blockDim.x) Wls[i] = Wl[i];
    __syncthreads();

    int w = (blockIdx.x * blockDim.x + threadIdx.x) >> 5;
    int lane = threadIdx.x & 31;
    if (w >= n) return;
    int beg = g_rowptr[w], end = g_rowptr[w + 1];
    float2 edn = g_ed23[w];

    float S2 = 0.f, S3 = 0.f;
    for (int i = beg + lane; i < end; i += 32) {
        float2 es = g_es23[g_col[i]];
        float p2 = __expf(lrelu(es.x + edn.x));
        float p3 = __expf(lrelu(es.y + edn.y));
        g_pp[i] = make_float2(p2, p3);
        S2 += p2;
        S3 += p3;
    }
#pragma unroll
    for (int o = 16; o; o >>= 1) {
        S2 += __shfl_xor_sync(0xffffffffu, S2, o);
        S3 += __shfl_xor_sync(0xffffffffu, S3, o);
    }
    float inv2 = 1.f / (S2 + 1e-16f);
    float pself = __expf(lrelu(g_es23[w].y + edn.y));
    S3 += pself;
    float inv3 = 1.f / (S3 + 1e-16f);
    if (lane == 0) g_dai[w] = make_float2(edn.x, inv2);
    __syncwarp();

    const __half2* hp = (const __half2*)g_h23h;
    float aM0 = 0.f, aV0 = 0.f, aM1 = 0.f, aV1 = 0.f;
    int i = beg;
    for (; i + 2 <= end; i += 2) {
        int s0 = g_col[i], s1 = g_col[i + 1];
        float2 pp0 = g_pp[i], pp1 = g_pp[i + 1];
        float2 h0 = __half22float2(hp[(size_t)s0 * 32 + lane]);
        float2 h1 = __half22float2(hp[(size_t)s1 * 32 + lane]);
        aM0 += pp0.x * h0.x;
        aV0 += pp0.y * h0.y;
        aM1 += pp1.x * h1.x;
        aV1 += pp1.y * h1.y;
    }
    if (i < end) {
        float2 pp0 = g_pp[i];
        float2 h0 = __half22float2(hp[(size_t)g_col[i] * 32 + lane]);
        aM0 += pp0.x * h0.x;
        aV0 += pp0.y * h0.y;
    }
    float accM = aM0 + aM1, accV = aV0 + aV1;
    float h3self = __half22float2(hp[(size_t)w * 32 + lane]).y;
    accV = (accV + pself * h3self) * inv3 + __ldg(b3 + lane);
    out_var[(size_t)w * 32 + lane] = accV;

    float mp = accM * inv2 + __ldg(b2 + lane);
    mp = fmaxf(mp, 0.f);
    float acc = 0.f;
#pragma unroll
    for (int f = 0; f < 32; f++) {
        float v = __shfl_sync(0xffffffffu, mp, f);
        acc += v * Wls[f * 32 + lane];
    }
    out_mean[(size_t)w * 32 + lane] = acc + __ldg(bl + lane);
}

// edge-parallel alpha: fp32 path, 2 random gathers/edge, coalesced write.
__global__ void k_alpha(const int* __restrict__ src, const int* __restrict__ dst,
                        float* __restrict__ out_alpha, int e) {
    int i = (blockIdx.x * blockDim.x + threadIdx.x) * 4;
    if (i + 3 < e) {
        int4 s = *(const int4*)(src + i);
        int4 d = *(const int4*)(dst + i);
        float2 a0 = g_dai[d.x], a1 = g_dai[d.y], a2 = g_dai[d.z], a3 = g_dai[d.w];
        float e0 = g_es23[s.x].x, e1 = g_es23[s.y].x;
        float e2 = g_es23[s.z].x, e3 = g_es23[s.w].x;
        float4 r;
        r.x = __expf(lrelu(e0 + a0.x)) * a0.y;
        r.y = __expf(lrelu(e1 + a1.x)) * a1.y;
        r.z = __expf(lrelu(e2 + a2.x)) * a2.y;
        r.w = __expf(lrelu(e3 + a3.x)) * a3.y;
        *(float4*)(out_alpha + i) = r;
    } else {
        for (int j = i; j < e; j++) {
            float2 a = g_dai[dst[j]];
            out_alpha[j] = __expf(lrelu(g_es23[src[j]].x + a.x)) * a.y;
        }
    }
}

// ---------------------------------------------------------------------------
extern "C" void kernel_launch(void* const* d_in, const int* in_sizes, int n_in,
                              void* d_out, int out_size) {
    const float* x   = (const float*)d_in[0];
    const int*   ei  = (const int*)  d_in[1];
    const float* W1  = (const float*)d_in[2];
    const float* a1s = (const float*)d_in[3];
    const float* a1d = (const float*)d_in[4];
    const float* b1  = (const float*)d_in[5];
    const float* W2  = (const float*)d_in[6];
    const float* a2s = (const float*)d_in[7];
    const float* a2d = (const float*)d_in[8];
    const float* b2  = (const float*)d_in[9];
    const float* W3  = (const float*)d_in[10];
    const float* a3s = (const float*)d_in[11];
    const float* a3d = (const float*)d_in[12];
    const float* b3  = (const float*)d_in[13];
    const float* Wl  = (const float*)d_in[14];
    const float* bl  = (const float*)d_in[15];

    const int n = in_sizes[0] / 256;
    const int e = in_sizes[1] / 2;
    const int* src = ei;
    const int* dst = ei + e;

    float* out_mean  = (float*)d_out;
    float* out_var   = out_mean + (size_t)n * 32;
    float* out_alpha = out_var + (size_t)n * 32;

    const int TB = 256;
    int gridN  = (n + TB - 1) / TB;
    int gridE4 = ((e + 3) / 4 + TB - 1) / TB;
    int gridE8 = ((e + 7) / 8 + TB - 1) / TB;
    int gridM  = (n + 127) / 128;
    int gridW  = (n * 32 + TB - 1) / TB;
    int nb     = (n + 1023) / 1024;

    static cudaStream_t s_b = nullptr;
    static cudaEvent_t ev_fork = nullptr, ev_join = nullptr;
    if (s_b == nullptr) {
        cudaStreamCreateWithFlags(&s_b, cudaStreamNonBlocking);
        cudaEventCreateWithFlags(&ev_fork, cudaEventDisableTiming);
        cudaEventCreateWithFlags(&ev_join, cudaEventDisableTiming);
    }

    // fork: CSR chain on s_b, gemm1 on default stream
    cudaEventRecord(ev_fork, 0);
    cudaStreamWaitEvent(s_b, ev_fork, 0);
    k_hist<<<gridE4, TB, 0, s_b>>>(dst, e);
    k_scan1<<<nb, TB, 0, s_b>>>(n);
    k_scan23<<<gridN, TB, 0, s_b>>>(n, nb);
    k_scatter<<<gridE8, TB, 0, s_b>>>(src, dst, e);
    cudaEventRecord(ev_join, s_b);

    k_gemm_tc<0><<<gridM, TB>>>(x, W1, nullptr, a1s, a1d, a1s, a1d, n);

    // join: everything below needs both CSR and gemm1 results
    cudaStreamWaitEvent(0, ev_join, 0);
    k_agg1<<<gridW, TB>>>(b1, n);
    k_gemm_tc<1><<<gridM, TB>>>(nullptr, W2, W3, a2s, a2d, a3s, a3d, n);
    k_agg23<<<gridW, TB>>>(b2, b3, Wl, bl, out_mean, out_var, n);
    k_alpha<<<gridE4, TB>>>(src, dst, out_alpha, e);
}